// round 12
// baseline (speedup 1.0000x reference)
#include <cuda_runtime.h>
#include <cuda_fp16.h>
#include <cstdint>

#define NB 512
#define NF 64
#define NP 2016
#define NE 32
#define NGROUPS (NP + NF)

// strides in 4B words (stride % 32 == 4 and row stride 16B-aligned for ldmatrix)
#define SW0 36   // W0^T [128 n][32 kp-words + 4 pad]   row = 144 B
#define SW1 68   // W1^T [128 n][64 kp-words + 4 pad]   row = 272 B

// SMEM byte offsets
#define OFF_WT1 0        // 128*68*4 = 34816
#define OFF_WT0 34816    // 128*36*4 = 18432
#define OFF_B0  53248
#define OFF_B1  53760
#define OFF_W2  54272
#define SMEM_TOTAL 54784

__device__ __forceinline__ uint32_t pack_h2(float lo, float hi) {
    uint32_t d;
    asm("cvt.rn.f16x2.f32 %0, %1, %2;" : "=r"(d) : "f"(hi), "f"(lo));
    return d;
}
__device__ __forceinline__ uint32_t smem_u32(const void* p) {
    uint32_t a;
    asm("{ .reg .u64 t; cvta.to.shared.u64 t, %1; cvt.u32.u64 %0, t; }" : "=r"(a) : "l"(p));
    return a;
}

#define MMA_F16(d, a0, a1, a2, a3, bv0, bv1)                                   \
    asm volatile("mma.sync.aligned.m16n8k16.row.col.f32.f16.f16.f32 "          \
                 "{%0,%1,%2,%3}, {%4,%5,%6,%7}, {%8,%9}, {%0,%1,%2,%3};"       \
                 : "+f"((d)[0]), "+f"((d)[1]), "+f"((d)[2]), "+f"((d)[3])      \
                 : "r"(a0), "r"(a1), "r"(a2), "r"(a3), "r"(bv0), "r"(bv1))

// x4: {b0,b1} = B-frag for n-tile t (kp+0 / kp+4), {b2,b3} = n-tile t+1
#define LDSM_X4(b0, b1, b2, b3, addr)                                          \
    asm volatile("ldmatrix.sync.aligned.m8n8.x4.shared.b16 {%0,%1,%2,%3}, [%4];" \
                 : "=r"(b0), "=r"(b1), "=r"(b2), "=r"(b3) : "r"(addr))

__device__ __forceinline__ float smooth_z(float z) {
    float s = fmaf(-2.0f * z * z, z, fmaf(1.5f, z, 0.5f));
    s = (z <= -0.5f) ? 0.0f : s;
    s = (z >=  0.5f) ? 1.0f : s;
    return s;
}

extern __shared__ char smem_raw[];

__global__ __launch_bounds__(128, 4)
void dnamite_h16_kernel(const int*   __restrict__ mains,
                        const int*   __restrict__ pairs,
                        const float* __restrict__ emb,
                        const float* __restrict__ mw0, const float* __restrict__ mw1,
                        const float* __restrict__ mw2, const float* __restrict__ mb0,
                        const float* __restrict__ mb1, const float* __restrict__ mb2,
                        const float* __restrict__ z_main,
                        const float* __restrict__ pw0, const float* __restrict__ pw1,
                        const float* __restrict__ pw2, const float* __restrict__ pb0,
                        const float* __restrict__ pb1, const float* __restrict__ pb2,
                        const float* __restrict__ z_pairs,
                        const int*   __restrict__ pairs_list,
                        const int*   __restrict__ feat_off,
                        float*       __restrict__ out)
{
    uint32_t* WT1s = (uint32_t*)(smem_raw + OFF_WT1);
    uint32_t* WT0s = (uint32_t*)(smem_raw + OFF_WT0);
    float*    b0s  = (float*)(smem_raw + OFF_B0);
    float*    b1s  = (float*)(smem_raw + OFF_B1);
    float*    w2s  = (float*)(smem_raw + OFF_W2);

    const int tid  = threadIdx.x;
    const int g    = blockIdx.x;
    const bool is_pair = (g < NP);

    const int lane = tid & 31;
    const int qr   = lane >> 2;   // 0..7
    const int qc   = lane & 3;    // 0..3
    const int w    = tid >> 5;    // warp 0..3 -> rows [w*32, w*32+32)

    // ldmatrix lane-address decomposition
    const int lm_thi = lane >> 4;
    const int lm_tlo = (lane >> 3) & 1;
    const int lm_r   = lane & 7;

    const float *w0g, *w1g, *b0g, *b1g, *w2g;
    float b2v, zv;
    int offi = 0, offj = 0, K0, f_ = 0;
    if (is_pair) {
        K0  = 64;
        w0g = pw0 + (size_t)g * 64 * 128;
        w1g = pw1 + (size_t)g * 128 * 128;
        w2g = pw2 + (size_t)g * 128;
        b0g = pb0 + (size_t)g * 128;
        b1g = pb1 + (size_t)g * 128;
        b2v = pb2[g];
        zv  = smooth_z(z_pairs[g]);
        offi = feat_off[pairs_list[2 * g + 0]];
        offj = feat_off[pairs_list[2 * g + 1]];
    } else {
        f_  = g - NP;
        K0  = 32;
        w0g = mw0 + (size_t)f_ * 32 * 128;
        w1g = mw1 + (size_t)f_ * 128 * 128;
        w2g = mw2 + (size_t)f_ * 128;
        b0g = mb0 + (size_t)f_ * 128;
        b1g = mb1 + (size_t)f_ * 128;
        b2v = mb2[f_];
        zv  = smooth_z(z_main[f_]);
        offi = feat_off[f_];
    }

    // ---- weights -> SMEM as W^T [n][k-pair] in f16x2 ----
    for (int i = tid; i < 128 * (K0 >> 1); i += 128) {
        int n = i & 127, kp = i >> 7;
        float v0 = w0g[(2 * kp + 0) * 128 + n];
        float v1 = w0g[(2 * kp + 1) * 128 + n];
        WT0s[n * SW0 + kp] = pack_h2(v0, v1);
    }
    if (!is_pair) {
        for (int i = tid; i < 128 * 16; i += 128) {
            int n = i & 127, kp = i >> 7;
            WT0s[n * SW0 + 16 + kp] = 0u;
        }
    }
    for (int i = tid; i < 128 * 64; i += 128) {
        int n = i & 127, kp = i >> 7;
        float v0 = w1g[(2 * kp + 0) * 128 + n];
        float v1 = w1g[(2 * kp + 1) * 128 + n];
        WT1s[n * SW1 + kp] = pack_h2(v0, v1);
    }
    if (tid < 128) {
        b0s[tid] = b0g[tid];
        b1s[tid] = b1g[tid];
        w2s[tid] = w2g[tid];
    }
    __syncthreads();   // weights visible; SMEM read-only from here on

    const uint32_t sb = smem_u32(smem_raw);
    const uint32_t lmw0 = sb + OFF_WT0 + 4u * ((uint32_t)(lm_thi * 8 + lm_r) * SW0 + lm_tlo * 4);
    const uint32_t lmw1 = sb + OFF_WT1 + 4u * ((uint32_t)(lm_thi * 8 + lm_r) * SW1 + lm_tlo * 4);

    #pragma unroll 1
    for (int mtm = 0; mtm < 8; mtm++) {      // (mt, m) flattened: 8 x 16-row slabs
        const int mt = mtm >> 1, m = mtm & 1;
        const int rowbase = mt * 128 + w * 32 + m * 16;

        // ---- A fragments straight from gmem ----
        uint32_t A0[4][4];
        #pragma unroll
        for (int t = 0; t < 2; t++) {
            const int row = rowbase + t * 8 + qr;
            const float* ei;
            const float* ej = nullptr;
            if (is_pair) {
                int2 bp = *(const int2*)&pairs[((size_t)row * NP + g) * 2];
                ei = emb + (size_t)(offi + bp.x) * NE;
                ej = emb + (size_t)(offj + bp.y) * NE;
            } else {
                int bin = mains[(size_t)row * NF + f_];
                ei = emb + (size_t)(offi + bin) * NE;
            }
            const int k0 = 2 * qc;
            #pragma unroll
            for (int ks = 0; ks < 2; ks++) {
                float2 x0 = *(const float2*)(ei + 16 * ks + k0);
                float2 x1 = *(const float2*)(ei + 16 * ks + k0 + 8);
                A0[ks][t]     = pack_h2(x0.x, x0.y);
                A0[ks][t + 2] = pack_h2(x1.x, x1.y);
            }
            if (is_pair) {
                #pragma unroll
                for (int ks = 2; ks < 4; ks++) {
                    float2 x0 = *(const float2*)(ej + 16 * (ks - 2) + k0);
                    float2 x1 = *(const float2*)(ej + 16 * (ks - 2) + k0 + 8);
                    A0[ks][t]     = pack_h2(x0.x, x0.y);
                    A0[ks][t + 2] = pack_h2(x1.x, x1.y);
                }
            } else {
                #pragma unroll
                for (int ks = 2; ks < 4; ks++) {
                    A0[ks][t]     = 0u;
                    A0[ks][t + 2] = 0u;
                }
            }
        }

        // ---- layer 0: H (registers, packed f16x2), N in 4 chunks of 32 ----
        uint32_t Hp0[16], Hp1[16];
        #pragma unroll
        for (int c = 0; c < 4; c++) {
            float acc[4][4];
            #pragma unroll
            for (int t = 0; t < 4; t++)
                #pragma unroll
                for (int j = 0; j < 4; j++) acc[t][j] = 0.0f;

            #pragma unroll
            for (int ks = 0; ks < 4; ks++) {
                #pragma unroll
                for (int tp = 0; tp < 2; tp++) {
                    uint32_t b0, b1, b2, b3;
                    LDSM_X4(b0, b1, b2, b3,
                            lmw0 + 4u * ((uint32_t)(c * 32 + tp * 16) * SW0 + ks * 8));
                    MMA_F16(acc[2 * tp],     A0[ks][0], A0[ks][1], A0[ks][2], A0[ks][3], b0, b1);
                    MMA_F16(acc[2 * tp + 1], A0[ks][0], A0[ks][1], A0[ks][2], A0[ks][3], b2, b3);
                }
            }
            #pragma unroll
            for (int t = 0; t < 4; t++) {
                int tt  = c * 4 + t;
                int col = tt * 8 + 2 * qc;
                float ba = b0s[col], bb = b0s[col + 1];
                Hp0[tt] = pack_h2(fmaxf(acc[t][0] + ba, 0.0f), fmaxf(acc[t][1] + bb, 0.0f));
                Hp1[tt] = pack_h2(fmaxf(acc[t][2] + ba, 0.0f), fmaxf(acc[t][3] + bb, 0.0f));
            }
        }

        // ---- layer 1 (A from registers), N in 4 chunks + fused epilogue ----
        float s0 = 0.0f, s1 = 0.0f;
        #pragma unroll
        for (int c = 0; c < 4; c++) {
            float acc[4][4];
            #pragma unroll
            for (int t = 0; t < 4; t++)
                #pragma unroll
                for (int j = 0; j < 4; j++) acc[t][j] = 0.0f;

            #pragma unroll
            for (int K = 0; K < 8; K++) {
                #pragma unroll
                for (int tp = 0; tp < 2; tp++) {
                    uint32_t b0, b1, b2, b3;
                    LDSM_X4(b0, b1, b2, b3,
                            lmw1 + 4u * ((uint32_t)(c * 32 + tp * 16) * SW1 + K * 8));
                    MMA_F16(acc[2 * tp],     Hp0[2 * K], Hp1[2 * K], Hp0[2 * K + 1], Hp1[2 * K + 1], b0, b1);
                    MMA_F16(acc[2 * tp + 1], Hp0[2 * K], Hp1[2 * K], Hp0[2 * K + 1], Hp1[2 * K + 1], b2, b3);
                }
            }
            #pragma unroll
            for (int t = 0; t < 4; t++) {
                int col = (c * 4 + t) * 8 + 2 * qc;
                float ba = b1s[col], bb = b1s[col + 1];
                float wa = w2s[col], wb2 = w2s[col + 1];
                s0 += fmaxf(acc[t][0] + ba, 0.0f) * wa + fmaxf(acc[t][1] + bb, 0.0f) * wb2;
                s1 += fmaxf(acc[t][2] + ba, 0.0f) * wa + fmaxf(acc[t][3] + bb, 0.0f) * wb2;
            }
        }

        // quad-reduce over qc and accumulate
        s0 += __shfl_xor_sync(0xFFFFFFFF, s0, 1);
        s0 += __shfl_xor_sync(0xFFFFFFFF, s0, 2);
        s1 += __shfl_xor_sync(0xFFFFFFFF, s1, 1);
        s1 += __shfl_xor_sync(0xFFFFFFFF, s1, 2);
        if (qc == 0) {
            int row = rowbase + qr;
            atomicAdd(&out[row],     zv * (s0 + b2v));
            atomicAdd(&out[row + 8], zv * (s1 + b2v));
        }
    }
}

extern "C" void kernel_launch(void* const* d_in, const int* in_sizes, int n_in,
                              void* d_out, int out_size) {
    const int*   mains      = (const int*)  d_in[0];
    const int*   pairs      = (const int*)  d_in[1];
    const float* emb        = (const float*)d_in[2];
    const float* mw0        = (const float*)d_in[3];
    const float* mw1        = (const float*)d_in[4];
    const float* mw2        = (const float*)d_in[5];
    const float* mb0        = (const float*)d_in[6];
    const float* mb1        = (const float*)d_in[7];
    const float* mb2        = (const float*)d_in[8];
    const float* z_main     = (const float*)d_in[9];
    const float* pw0        = (const float*)d_in[10];
    const float* pw1        = (const float*)d_in[11];
    const float* pw2        = (const float*)d_in[12];
    const float* pb0        = (const float*)d_in[13];
    const float* pb1        = (const float*)d_in[14];
    const float* pb2        = (const float*)d_in[15];
    const float* z_pairs    = (const float*)d_in[16];
    const int*   pairs_list = (const int*)  d_in[17];
    const int*   feat_off   = (const int*)  d_in[18];
    float* out = (float*)d_out;

    static int configured = 0;
    if (!configured) {
        cudaFuncSetAttribute(dnamite_h16_kernel,
                             cudaFuncAttributeMaxDynamicSharedMemorySize, SMEM_TOTAL);
        configured = 1;
    }
    cudaMemsetAsync(out, 0, NB * sizeof(float), 0);
    dnamite_h16_kernel<<<NGROUPS, 128, SMEM_TOTAL>>>(
        mains, pairs, emb, mw0, mw1, mw2, mb0, mb1, mb2, z_main,
        pw0, pw1, pw2, pb0, pb1, pb2, z_pairs, pairs_list, feat_off, out);
}

// round 13
// speedup vs baseline: 1.0829x; 1.0829x over previous
#include <cuda_runtime.h>
#include <cuda_fp16.h>
#include <cstdint>

#define NB 512
#define NF 64
#define NP 2016
#define NE 32
#define NGROUPS (NP + NF)

// strides in 4B words (stride % 32 == 4 and row stride 16B-aligned for ldmatrix)
#define SW0 36   // W0^T [128 n][32 kp-words + 4 pad]   row = 144 B
#define SW1 68   // W1^T [128 n][64 kp-words + 4 pad]   row = 272 B

// SMEM byte offsets
#define OFF_WT1 0        // 128*68*4 = 34816
#define OFF_WT0 34816    // 128*36*4 = 18432
#define OFF_B0  53248
#define OFF_B1  53760
#define OFF_W2  54272
#define SMEM_TOTAL 54784

__device__ __forceinline__ uint32_t pack_h2(float lo, float hi) {
    uint32_t d;
    asm("cvt.rn.f16x2.f32 %0, %1, %2;" : "=r"(d) : "f"(hi), "f"(lo));
    return d;
}
__device__ __forceinline__ uint32_t smem_u32(const void* p) {
    uint32_t a;
    asm("{ .reg .u64 t; cvta.to.shared.u64 t, %1; cvt.u32.u64 %0, t; }" : "=r"(a) : "l"(p));
    return a;
}

#define MMA_F16(d, a0, a1, a2, a3, bv0, bv1)                                   \
    asm volatile("mma.sync.aligned.m16n8k16.row.col.f32.f16.f16.f32 "          \
                 "{%0,%1,%2,%3}, {%4,%5,%6,%7}, {%8,%9}, {%0,%1,%2,%3};"       \
                 : "+f"((d)[0]), "+f"((d)[1]), "+f"((d)[2]), "+f"((d)[3])      \
                 : "r"(a0), "r"(a1), "r"(a2), "r"(a3), "r"(bv0), "r"(bv1))

// x4 over 16 n-rows: {b0,b1} = B-frag n-tile 2c (kp+0 / kp+4), {b2,b3} = n-tile 2c+1
#define LDSM_X4(b0, b1, b2, b3, addr)                                          \
    asm volatile("ldmatrix.sync.aligned.m8n8.x4.shared.b16 {%0,%1,%2,%3}, [%4];" \
                 : "=r"(b0), "=r"(b1), "=r"(b2), "=r"(b3) : "r"(addr))

__device__ __forceinline__ float smooth_z(float z) {
    float s = fmaf(-2.0f * z * z, z, fmaf(1.5f, z, 0.5f));
    s = (z <= -0.5f) ? 0.0f : s;
    s = (z >=  0.5f) ? 1.0f : s;
    return s;
}

extern __shared__ char smem_raw[];

__global__ __launch_bounds__(128, 4)
void dnamite_h16_kernel(const int*   __restrict__ mains,
                        const int*   __restrict__ pairs,
                        const float* __restrict__ emb,
                        const float* __restrict__ mw0, const float* __restrict__ mw1,
                        const float* __restrict__ mw2, const float* __restrict__ mb0,
                        const float* __restrict__ mb1, const float* __restrict__ mb2,
                        const float* __restrict__ z_main,
                        const float* __restrict__ pw0, const float* __restrict__ pw1,
                        const float* __restrict__ pw2, const float* __restrict__ pb0,
                        const float* __restrict__ pb1, const float* __restrict__ pb2,
                        const float* __restrict__ z_pairs,
                        const int*   __restrict__ pairs_list,
                        const int*   __restrict__ feat_off,
                        float*       __restrict__ out)
{
    uint32_t* WT1s = (uint32_t*)(smem_raw + OFF_WT1);
    uint32_t* WT0s = (uint32_t*)(smem_raw + OFF_WT0);
    float*    b0s  = (float*)(smem_raw + OFF_B0);
    float*    b1s  = (float*)(smem_raw + OFF_B1);
    float*    w2s  = (float*)(smem_raw + OFF_W2);

    const int tid  = threadIdx.x;
    const int g    = blockIdx.x;
    const bool is_pair = (g < NP);

    const int lane = tid & 31;
    const int qr   = lane >> 2;   // 0..7
    const int qc   = lane & 3;    // 0..3
    const int w    = tid >> 5;    // warp 0..3 -> rows [w*32, w*32+32)

    // ldmatrix lane-address decomposition
    const int lm_thi = lane >> 4;
    const int lm_tlo = (lane >> 3) & 1;
    const int lm_r   = lane & 7;

    const float *w0g, *w1g, *b0g, *b1g, *w2g;
    float b2v, zv;
    int offi = 0, offj = 0, K0, f_ = 0;
    if (is_pair) {
        K0  = 64;
        w0g = pw0 + (size_t)g * 64 * 128;
        w1g = pw1 + (size_t)g * 128 * 128;
        w2g = pw2 + (size_t)g * 128;
        b0g = pb0 + (size_t)g * 128;
        b1g = pb1 + (size_t)g * 128;
        b2v = pb2[g];
        zv  = smooth_z(z_pairs[g]);
        offi = feat_off[pairs_list[2 * g + 0]];
        offj = feat_off[pairs_list[2 * g + 1]];
    } else {
        f_  = g - NP;
        K0  = 32;
        w0g = mw0 + (size_t)f_ * 32 * 128;
        w1g = mw1 + (size_t)f_ * 128 * 128;
        w2g = mw2 + (size_t)f_ * 128;
        b0g = mb0 + (size_t)f_ * 128;
        b1g = mb1 + (size_t)f_ * 128;
        b2v = mb2[f_];
        zv  = smooth_z(z_main[f_]);
        offi = feat_off[f_];
    }

    // ---- weights -> SMEM as W^T [n][k-pair] in f16x2 ----
    for (int i = tid; i < 128 * (K0 >> 1); i += 128) {
        int n = i & 127, kp = i >> 7;
        float v0 = w0g[(2 * kp + 0) * 128 + n];
        float v1 = w0g[(2 * kp + 1) * 128 + n];
        WT0s[n * SW0 + kp] = pack_h2(v0, v1);
    }
    if (!is_pair) {
        for (int i = tid; i < 128 * 16; i += 128) {
            int n = i & 127, kp = i >> 7;
            WT0s[n * SW0 + 16 + kp] = 0u;
        }
    }
    for (int i = tid; i < 128 * 64; i += 128) {
        int n = i & 127, kp = i >> 7;
        float v0 = w1g[(2 * kp + 0) * 128 + n];
        float v1 = w1g[(2 * kp + 1) * 128 + n];
        WT1s[n * SW1 + kp] = pack_h2(v0, v1);
    }
    if (tid < 128) {
        b0s[tid] = b0g[tid];
        b1s[tid] = b1g[tid];
        w2s[tid] = w2g[tid];
    }
    __syncthreads();   // weights visible; SMEM read-only from here on

    const uint32_t sb = smem_u32(smem_raw);
    const uint32_t lmw0 = sb + OFF_WT0 + 4u * ((uint32_t)(lm_thi * 8 + lm_r) * SW0 + lm_tlo * 4);
    const uint32_t lmw1 = sb + OFF_WT1 + 4u * ((uint32_t)(lm_thi * 8 + lm_r) * SW1 + lm_tlo * 4);

    #pragma unroll 1
    for (int mt = 0; mt < 4; mt++) {
        const int Mbase = mt * 128;

        // ---- A fragments straight from gmem (no SMEM, no barriers) ----
        uint32_t A0[2][4][4];
        #pragma unroll
        for (int m = 0; m < 2; m++) {
            #pragma unroll
            for (int t = 0; t < 2; t++) {
                const int row = Mbase + w * 32 + m * 16 + t * 8 + qr;
                const float* ei;
                const float* ej = nullptr;
                if (is_pair) {
                    int2 bp = *(const int2*)&pairs[((size_t)row * NP + g) * 2];
                    ei = emb + (size_t)(offi + bp.x) * NE;
                    ej = emb + (size_t)(offj + bp.y) * NE;
                } else {
                    int bin = mains[(size_t)row * NF + f_];
                    ei = emb + (size_t)(offi + bin) * NE;
                }
                const int k0 = 2 * qc;
                #pragma unroll
                for (int ks = 0; ks < 2; ks++) {
                    float2 x0 = *(const float2*)(ei + 16 * ks + k0);
                    float2 x1 = *(const float2*)(ei + 16 * ks + k0 + 8);
                    A0[m][ks][t]     = pack_h2(x0.x, x0.y);
                    A0[m][ks][t + 2] = pack_h2(x1.x, x1.y);
                }
                if (is_pair) {
                    #pragma unroll
                    for (int ks = 2; ks < 4; ks++) {
                        float2 x0 = *(const float2*)(ej + 16 * (ks - 2) + k0);
                        float2 x1 = *(const float2*)(ej + 16 * (ks - 2) + k0 + 8);
                        A0[m][ks][t]     = pack_h2(x0.x, x0.y);
                        A0[m][ks][t + 2] = pack_h2(x1.x, x1.y);
                    }
                } else {
                    #pragma unroll
                    for (int ks = 2; ks < 4; ks++) {
                        A0[m][ks][t]     = 0u;
                        A0[m][ks][t + 2] = 0u;
                    }
                }
            }
        }

        // ---- layer 0: H (registers, packed f16x2), N in 8 chunks of 16 ----
        uint32_t Hp0[2][16], Hp1[2][16];
        #pragma unroll
        for (int c = 0; c < 8; c++) {
            float acc[2][2][4];
            #pragma unroll
            for (int m = 0; m < 2; m++)
                #pragma unroll
                for (int t = 0; t < 2; t++)
                    #pragma unroll
                    for (int j = 0; j < 4; j++) acc[m][t][j] = 0.0f;

            #pragma unroll
            for (int ks = 0; ks < 4; ks++) {
                uint32_t b0, b1, b2, b3;
                LDSM_X4(b0, b1, b2, b3,
                        lmw0 + 4u * ((uint32_t)(c * 16) * SW0 + ks * 8));
                MMA_F16(acc[0][0], A0[0][ks][0], A0[0][ks][1], A0[0][ks][2], A0[0][ks][3], b0, b1);
                MMA_F16(acc[1][0], A0[1][ks][0], A0[1][ks][1], A0[1][ks][2], A0[1][ks][3], b0, b1);
                MMA_F16(acc[0][1], A0[0][ks][0], A0[0][ks][1], A0[0][ks][2], A0[0][ks][3], b2, b3);
                MMA_F16(acc[1][1], A0[1][ks][0], A0[1][ks][1], A0[1][ks][2], A0[1][ks][3], b2, b3);
            }
            #pragma unroll
            for (int t = 0; t < 2; t++) {
                int tt  = c * 2 + t;
                int col = tt * 8 + 2 * qc;
                float ba = b0s[col], bb = b0s[col + 1];
                #pragma unroll
                for (int m = 0; m < 2; m++) {
                    Hp0[m][tt] = pack_h2(fmaxf(acc[m][t][0] + ba, 0.0f), fmaxf(acc[m][t][1] + bb, 0.0f));
                    Hp1[m][tt] = pack_h2(fmaxf(acc[m][t][2] + ba, 0.0f), fmaxf(acc[m][t][3] + bb, 0.0f));
                }
            }
        }

        // ---- layer 1 (A from registers), N in 8 chunks of 16 + fused epilogue ----
        float s0[2] = {0.0f, 0.0f}, s1[2] = {0.0f, 0.0f};
        #pragma unroll
        for (int c = 0; c < 8; c++) {
            float acc[2][2][4];
            #pragma unroll
            for (int m = 0; m < 2; m++)
                #pragma unroll
                for (int t = 0; t < 2; t++)
                    #pragma unroll
                    for (int j = 0; j < 4; j++) acc[m][t][j] = 0.0f;

            #pragma unroll
            for (int K = 0; K < 8; K++) {
                uint32_t b0, b1, b2, b3;
                LDSM_X4(b0, b1, b2, b3,
                        lmw1 + 4u * ((uint32_t)(c * 16) * SW1 + K * 8));
                MMA_F16(acc[0][0], Hp0[0][2 * K], Hp1[0][2 * K], Hp0[0][2 * K + 1], Hp1[0][2 * K + 1], b0, b1);
                MMA_F16(acc[1][0], Hp0[1][2 * K], Hp1[1][2 * K], Hp0[1][2 * K + 1], Hp1[1][2 * K + 1], b0, b1);
                MMA_F16(acc[0][1], Hp0[0][2 * K], Hp1[0][2 * K], Hp0[0][2 * K + 1], Hp1[0][2 * K + 1], b2, b3);
                MMA_F16(acc[1][1], Hp0[1][2 * K], Hp1[1][2 * K], Hp0[1][2 * K + 1], Hp1[1][2 * K + 1], b2, b3);
            }
            #pragma unroll
            for (int t = 0; t < 2; t++) {
                int col = (c * 2 + t) * 8 + 2 * qc;
                float ba = b1s[col], bb = b1s[col + 1];
                float wa = w2s[col], wb2 = w2s[col + 1];
                #pragma unroll
                for (int m = 0; m < 2; m++) {
                    s0[m] += fmaxf(acc[m][t][0] + ba, 0.0f) * wa + fmaxf(acc[m][t][1] + bb, 0.0f) * wb2;
                    s1[m] += fmaxf(acc[m][t][2] + ba, 0.0f) * wa + fmaxf(acc[m][t][3] + bb, 0.0f) * wb2;
                }
            }
        }

        // quad-reduce over qc and accumulate
        #pragma unroll
        for (int m = 0; m < 2; m++) {
            s0[m] += __shfl_xor_sync(0xFFFFFFFF, s0[m], 1);
            s0[m] += __shfl_xor_sync(0xFFFFFFFF, s0[m], 2);
            s1[m] += __shfl_xor_sync(0xFFFFFFFF, s1[m], 1);
            s1[m] += __shfl_xor_sync(0xFFFFFFFF, s1[m], 2);
        }
        if (qc == 0) {
            #pragma unroll
            for (int m = 0; m < 2; m++) {
                int row = Mbase + w * 32 + m * 16 + qr;
                atomicAdd(&out[row],     zv * (s0[m] + b2v));
                atomicAdd(&out[row + 8], zv * (s1[m] + b2v));
            }
        }
    }
}

extern "C" void kernel_launch(void* const* d_in, const int* in_sizes, int n_in,
                              void* d_out, int out_size) {
    const int*   mains      = (const int*)  d_in[0];
    const int*   pairs      = (const int*)  d_in[1];
    const float* emb        = (const float*)d_in[2];
    const float* mw0        = (const float*)d_in[3];
    const float* mw1        = (const float*)d_in[4];
    const float* mw2        = (const float*)d_in[5];
    const float* mb0        = (const float*)d_in[6];
    const float* mb1        = (const float*)d_in[7];
    const float* mb2        = (const float*)d_in[8];
    const float* z_main     = (const float*)d_in[9];
    const float* pw0        = (const float*)d_in[10];
    const float* pw1        = (const float*)d_in[11];
    const float* pw2        = (const float*)d_in[12];
    const float* pb0        = (const float*)d_in[13];
    const float* pb1        = (const float*)d_in[14];
    const float* pb2        = (const float*)d_in[15];
    const float* z_pairs    = (const float*)d_in[16];
    const int*   pairs_list = (const int*)  d_in[17];
    const int*   feat_off   = (const int*)  d_in[18];
    float* out = (float*)d_out;

    static int configured = 0;
    if (!configured) {
        cudaFuncSetAttribute(dnamite_h16_kernel,
                             cudaFuncAttributeMaxDynamicSharedMemorySize, SMEM_TOTAL);
        configured = 1;
    }
    cudaMemsetAsync(out, 0, NB * sizeof(float), 0);
    dnamite_h16_kernel<<<NGROUPS, 128, SMEM_TOTAL>>>(
        mains, pairs, emb, mw0, mw1, mw2, mb0, mb1, mb2, z_main,
        pw0, pw1, pw2, pb0, pb1, pb2, z_pairs, pairs_list, feat_off, out);
}